// round 11
// baseline (speedup 1.0000x reference)
#include <cuda_runtime.h>
#include <cuda_fp16.h>
#include <cstdint>
#include <cstddef>

#define I_DIM 512
#define O_DIM 512
#define KDIM  4096          // I_DIM * 8 degrees
#define TILE_M 128
#define TILE_N 128
#define KC     64           // K elems per chunk (8 i's x 8 degrees)
#define K_HALF 2048         // K per warp-group
#define NCHUNK_G (K_HALF / KC)   // 32 chunks per group
#define THREADS 256
#define PITCH  144          // 64 halves (128B) + 16B pad; 36 words -> +4 banks/row

#define COEF_SCALE   1024.0f
#define OUT_SCALE    (1.0f / 1024.0f)

// Transposed, scaled fp16 coefficients: Wh[o][k], k = i*8 + d
__device__ __align__(16) __half g_Wh[(size_t)O_DIM * KDIM];

// ---------------- helpers ----------------
__device__ __forceinline__ uint32_t smem_u32(const void* p) {
    uint32_t a;
    asm("{ .reg .u64 t; cvta.to.shared.u64 t, %1; cvt.u32.u64 %0, t; }"
        : "=r"(a) : "l"(p));
    return a;
}

__device__ __forceinline__ void sts128(uint32_t a, uint32_t v0, uint32_t v1,
                                       uint32_t v2, uint32_t v3) {
    asm volatile("st.shared.v4.b32 [%0], {%1,%2,%3,%4};"
                 :: "r"(a), "r"(v0), "r"(v1), "r"(v2), "r"(v3) : "memory");
}

__device__ __forceinline__ void lds128(uint32_t a, uint32_t* v) {
    asm volatile("ld.shared.v4.b32 {%0,%1,%2,%3}, [%4];"
                 : "=r"(v[0]), "=r"(v[1]), "=r"(v[2]), "=r"(v[3]) : "r"(a));
}

__device__ __forceinline__ void ldsm4(uint32_t* r, uint32_t addr) {
    asm volatile("ldmatrix.sync.aligned.m8n8.x4.shared.b16 {%0,%1,%2,%3}, [%4];"
                 : "=r"(r[0]), "=r"(r[1]), "=r"(r[2]), "=r"(r[3]) : "r"(addr));
}

// m16n8k16 fp16 MMA, f32 accumulate
__device__ __forceinline__ void mma16(float* c, const uint32_t* a, const uint32_t* b) {
    asm volatile(
        "mma.sync.aligned.m16n8k16.row.col.f32.f16.f16.f32 "
        "{%0,%1,%2,%3}, {%4,%5,%6,%7}, {%8,%9}, {%0,%1,%2,%3};"
        : "+f"(c[0]), "+f"(c[1]), "+f"(c[2]), "+f"(c[3])
        : "r"(a[0]), "r"(a[1]), "r"(a[2]), "r"(a[3]), "r"(b[0]), "r"(b[1]));
}

__device__ __forceinline__ uint32_t pack_h2(float lo, float hi) {
    __half2 h = __floats2half2_rn(lo, hi);
    return *reinterpret_cast<uint32_t*>(&h);
}

// accurate-enough tanh: 1 - 2/(exp(2x)+1); MUFU-based, err ~1e-6
__device__ __forceinline__ float fast_tanh(float x) {
    float e = __expf(2.0f * x);
    return 1.0f - __fdividef(2.0f, e + 1.0f);
}

// group barrier: named bar.sync over 128 threads
__device__ __forceinline__ void group_bar(int g) {
    asm volatile("bar.sync %0, %1;" :: "r"(1 + g), "r"(128) : "memory");
}

// ---------------- kernel 0: transpose + scale coeffs to fp16 ----------------
__global__ void prep_kernel(const float* __restrict__ coeffs) {
    int idx = blockIdx.x * blockDim.x + threadIdx.x;   // coalesced read
    int i = idx >> 12;
    int o = (idx >> 3) & 511;
    int d = idx & 7;
    g_Wh[((size_t)o << 12) + (i << 3) + d] =
        __float2half_rn(coeffs[idx] * COEF_SCALE);
}

// ---------------- kernel 1: split-K warp-group fp16 mma GEMM ----------------
// Per group: A stage 128*144=18432, B stage 18432; double buffered = 73728/group
#define G_STRIDE 73728u
#define ST_SIZE  18432u
#define SMEM_BYTES (2 * 73728)   // 147456

__global__ void __launch_bounds__(THREADS, 1)
gegen_kernel(const float* __restrict__ x, float* __restrict__ out) {
    extern __shared__ __align__(16) char smem[];
    const uint32_t sb = smem_u32(smem);
    const int tid  = threadIdx.x;
    const int lane = tid & 31;
    const int wid  = tid >> 5;
    const int g    = wid >> 2;          // k-group: 0 or 1
    const int lw   = wid & 3;           // warp within group
    const int gt   = tid & 127;         // thread within group
    const int b0 = blockIdx.x * TILE_M;
    const int o0 = blockIdx.y * TILE_N;
    const int wm = (lw & 1) * 64;       // warp m offset within group's tile
    const int wn = (lw >> 1) * 64;      // warp n offset

    const uint32_t gbase = sb + g * G_STRIDE;
    uint32_t aBase[2], bBase[2];
#pragma unroll
    for (int s = 0; s < 2; s++) {
        aBase[s] = gbase + s * ST_SIZE;
        bBase[s] = gbase + 2 * ST_SIZE + s * ST_SIZE;
    }

    float acc[4][8][4];
#pragma unroll
    for (int mf = 0; mf < 4; mf++)
#pragma unroll
        for (int nf = 0; nf < 8; nf++)
#pragma unroll
            for (int j = 0; j < 4; j++) acc[mf][nf][j] = 0.0f;

    // ---- ldmatrix per-lane offsets (relative to stage base) ----
    const int a_r = lane & 15;
    const int a_c = (lane >> 4) * 16;
    uint32_t aoff[4];
#pragma unroll
    for (int mf = 0; mf < 4; mf++)
        aoff[mf] = (uint32_t)(wm + mf * 16 + a_r) * PITCH + a_c;
    const int b_r = (lane & 7) + ((lane >> 4) & 1) * 8;
    const int b_c = ((lane >> 3) & 1) * 16;
    uint32_t boff[4];
#pragma unroll
    for (int p = 0; p < 4; p++)
        boff[p] = (uint32_t)(wn + p * 16 + b_r) * PITCH + b_c;

    // ---- producer bases: one thread per row within group ----
    // group g covers k in [g*2048, g*2048+2048)  ->  i in [g*256, g*256+256)
    const float* xrow = x + (size_t)(b0 + gt) * I_DIM + g * (K_HALF / 8);
    const __half* wrow = g_Wh + ((size_t)(o0 + gt) << 12) + g * K_HALF;
    const uint32_t a_sts = gt * PITCH;
    const uint32_t b_sts = gt * PITCH;

    auto cp_b = [&](int c, uint32_t bBuf) {
        const __half* src = wrow + c * KC;
#pragma unroll
        for (int j = 0; j < 8; j++) {
            asm volatile("cp.async.cg.shared.global [%0], [%1], 16;"
                         :: "r"(bBuf + b_sts + j * 16), "l"(src + j * 8)
                         : "memory");
        }
        asm volatile("cp.async.commit_group;" ::: "memory");
    };

    auto produce_a = [&](uint32_t aBuf, const float4& x0, const float4& x1) {
        const float xs[8] = {x0.x, x0.y, x0.z, x0.w, x1.x, x1.y, x1.z, x1.w};
#pragma unroll
        for (int ii = 0; ii < 8; ii++) {
            float t  = fast_tanh(xs[ii]);
            float t2 = t + t;
            float c0 = 1.0f, c1 = t2;
            float c2 = fmaf(t2, c1, -c0);
            float c3 = fmaf(t2, c2, -c1);
            float c4 = fmaf(t2, c3, -c2);
            float c5 = fmaf(t2, c4, -c3);
            float c6 = fmaf(t2, c5, -c4);
            float c7 = fmaf(t2, c6, -c5);
            sts128(aBuf + a_sts + ii * 16,
                   pack_h2(c0, c1), pack_h2(c2, c3),
                   pack_h2(c4, c5), pack_h2(c6, c7));
        }
    };

    auto consume = [&](uint32_t aBuf, uint32_t bBuf) {
#pragma unroll
        for (int ks = 0; ks < 4; ks++) {
            const uint32_t koff = ks * 32;
            uint32_t a[4][4], b[4][4];
#pragma unroll
            for (int mf = 0; mf < 4; mf++) ldsm4(a[mf], aBuf + aoff[mf] + koff);
#pragma unroll
            for (int p = 0; p < 4; p++)   ldsm4(b[p], bBuf + boff[p] + koff);
#pragma unroll
            for (int mf = 0; mf < 4; mf++)
#pragma unroll
                for (int nf = 0; nf < 8; nf++)
                    mma16(acc[mf][nf], a[mf], &b[nf >> 1][(nf & 1) * 2]);
        }
    };

    // ---- prologue: fill chunk 0 for this group ----
    float4 xa = *reinterpret_cast<const float4*>(xrow);
    float4 xb = *reinterpret_cast<const float4*>(xrow + 4);
    cp_b(0, bBase[0]);
    produce_a(aBase[0], xa, xb);
    xa = *reinterpret_cast<const float4*>(xrow + 8);     // chunk 1 x's
    xb = *reinterpret_cast<const float4*>(xrow + 12);

    // ---- main loop: groups run fully independently (named barriers) ----
#pragma unroll 1
    for (int c = 0; c < NCHUNK_G; c++) {
        asm volatile("cp.async.wait_group 0;" ::: "memory");
        group_bar(g);      // chunk c visible within group; buf (c+1)&1 free

        const int cur = c & 1, nxt = cur ^ 1;
        if (c + 1 < NCHUNK_G) cp_b(c + 1, bBase[nxt]);

        consume(aBase[cur], bBase[cur]);

        if (c + 1 < NCHUNK_G) {
            produce_a(aBase[nxt], xa, xb);
            if (c + 2 < NCHUNK_G) {
                xa = *reinterpret_cast<const float4*>(xrow + (c + 2) * 8);
                xb = *reinterpret_cast<const float4*>(xrow + (c + 2) * 8 + 4);
            }
        }
    }

    // ---- cross-group reduction: g1 -> smem, g0 adds and stores ----
    __syncthreads();
    const uint32_t red = sb + lw * 16384u;   // per warp-position region (16 KB)
    if (g == 1) {
#pragma unroll
        for (int mf = 0; mf < 4; mf++)
#pragma unroll
            for (int nf = 0; nf < 8; nf++) {
                uint32_t addr = red + (uint32_t)((mf * 8 + nf) * 32 + lane) * 16;
                sts128(addr,
                       __float_as_uint(acc[mf][nf][0]),
                       __float_as_uint(acc[mf][nf][1]),
                       __float_as_uint(acc[mf][nf][2]),
                       __float_as_uint(acc[mf][nf][3]));
            }
    }
    __syncthreads();
    if (g == 0) {
#pragma unroll
        for (int mf = 0; mf < 4; mf++) {
#pragma unroll
            for (int nf = 0; nf < 8; nf++) {
                uint32_t q[4];
                uint32_t addr = red + (uint32_t)((mf * 8 + nf) * 32 + lane) * 16;
                lds128(addr, q);
#pragma unroll
                for (int j = 0; j < 4; j++)
                    acc[mf][nf][j] += __uint_as_float(q[j]);
            }
            const int rbase = b0 + wm + mf * 16 + (lane >> 2);
#pragma unroll
            for (int h = 0; h < 2; h++) {
                float* op = out + (size_t)(rbase + h * 8) * O_DIM
                                + o0 + wn + (lane & 3) * 2;
#pragma unroll
                for (int nf = 0; nf < 8; nf++) {
                    float2 v;
                    v.x = acc[mf][nf][h * 2]     * OUT_SCALE;
                    v.y = acc[mf][nf][h * 2 + 1] * OUT_SCALE;
                    *reinterpret_cast<float2*>(op + nf * 8) = v;
                }
            }
        }
    }
}

// ---------------- launch ----------------
extern "C" void kernel_launch(void* const* d_in, const int* in_sizes, int n_in,
                              void* d_out, int out_size) {
    const float* x      = (const float*)d_in[0];
    const float* coeffs = (const float*)d_in[1];
    float* out          = (float*)d_out;

    const int B = in_sizes[0] / I_DIM;   // 16384

    prep_kernel<<<(I_DIM * O_DIM * 8) / 256, 256>>>(coeffs);

    cudaFuncSetAttribute(gegen_kernel,
                         cudaFuncAttributeMaxDynamicSharedMemorySize, SMEM_BYTES);

    dim3 grid(B / TILE_M, O_DIM / TILE_N);
    gegen_kernel<<<grid, THREADS, SMEM_BYTES>>>(x, out);
}

// round 12
// speedup vs baseline: 1.1164x; 1.1164x over previous
#include <cuda_runtime.h>
#include <cuda_fp16.h>
#include <cstdint>
#include <cstddef>

#define I_DIM 512
#define O_DIM 512
#define KDIM  4096          // I_DIM * 8 degrees
#define BATCH 16384
#define TILE_M 256
#define TILE_N 128
#define KC     64           // K elems per chunk
#define NCHUNK (KDIM / KC)  // 64
#define THREADS 256
#define PITCH  144          // 64 halves (128B) + 16B pad

#define COEF_SCALE   1024.0f
#define OUT_SCALE    (1.0f / 1024.0f)

// Transposed, scaled fp16 coefficients: Wh[o][k], k = i*8 + d
__device__ __align__(16) __half g_Wh[(size_t)O_DIM * KDIM];
// Materialized activation matrix: A[b][k] = U_d(tanh(x[b,i])), k = i*8+d
__device__ __align__(16) __half g_A[(size_t)BATCH * KDIM];

// ---------------- helpers ----------------
__device__ __forceinline__ uint32_t smem_u32(const void* p) {
    uint32_t a;
    asm("{ .reg .u64 t; cvta.to.shared.u64 t, %1; cvt.u32.u64 %0, t; }"
        : "=r"(a) : "l"(p));
    return a;
}

__device__ __forceinline__ void ldsm4(uint32_t* r, uint32_t addr) {
    asm volatile("ldmatrix.sync.aligned.m8n8.x4.shared.b16 {%0,%1,%2,%3}, [%4];"
                 : "=r"(r[0]), "=r"(r[1]), "=r"(r[2]), "=r"(r[3]) : "r"(addr));
}

// m16n8k16 fp16 MMA, f32 accumulate
__device__ __forceinline__ void mma16(float* c, const uint32_t* a, const uint32_t* b) {
    asm volatile(
        "mma.sync.aligned.m16n8k16.row.col.f32.f16.f16.f32 "
        "{%0,%1,%2,%3}, {%4,%5,%6,%7}, {%8,%9}, {%0,%1,%2,%3};"
        : "+f"(c[0]), "+f"(c[1]), "+f"(c[2]), "+f"(c[3])
        : "r"(a[0]), "r"(a[1]), "r"(a[2]), "r"(a[3]), "r"(b[0]), "r"(b[1]));
}

__device__ __forceinline__ uint32_t pack_h2(float lo, float hi) {
    __half2 h = __floats2half2_rn(lo, hi);
    return *reinterpret_cast<uint32_t*>(&h);
}

// accurate-enough tanh: 1 - 2/(exp(2x)+1); MUFU-based, err ~1e-6
__device__ __forceinline__ float fast_tanh(float x) {
    float e = __expf(2.0f * x);
    return 1.0f - __fdividef(2.0f, e + 1.0f);
}

// ---------------- kernel 0: transpose + scale coeffs to fp16 ----------------
__global__ void prep_kernel(const float* __restrict__ coeffs) {
    int idx = blockIdx.x * blockDim.x + threadIdx.x;   // coalesced read
    int i = idx >> 12;
    int o = (idx >> 3) & 511;
    int d = idx & 7;
    g_Wh[((size_t)o << 12) + (i << 3) + d] =
        __float2half_rn(coeffs[idx] * COEF_SCALE);
}

// ---------------- kernel 1: materialize A = Chebyshev-U polys of tanh(x) ----
// One thread handles 4 consecutive i's of one batch row: 16B read, 64B write.
__global__ void poly_kernel(const float* __restrict__ x) {
    int idx = blockIdx.x * blockDim.x + threadIdx.x;   // BATCH*128 threads
    int b  = idx >> 7;
    int ig = idx & 127;
    float4 xv = *reinterpret_cast<const float4*>(x + ((size_t)b << 9) + ig * 4);
    const float xs[4] = {xv.x, xv.y, xv.z, xv.w};
    uint32_t u[16];
#pragma unroll
    for (int r = 0; r < 4; r++) {
        float t  = fast_tanh(xs[r]);
        float t2 = t + t;
        float c0 = 1.0f, c1 = t2;
        float c2 = fmaf(t2, c1, -c0);
        float c3 = fmaf(t2, c2, -c1);
        float c4 = fmaf(t2, c3, -c2);
        float c5 = fmaf(t2, c4, -c3);
        float c6 = fmaf(t2, c5, -c4);
        float c7 = fmaf(t2, c6, -c5);
        u[r * 4 + 0] = pack_h2(c0, c1);
        u[r * 4 + 1] = pack_h2(c2, c3);
        u[r * 4 + 2] = pack_h2(c4, c5);
        u[r * 4 + 3] = pack_h2(c6, c7);
    }
    uint4* dst = reinterpret_cast<uint4*>(g_A + ((size_t)b << 12) + ig * 32);
#pragma unroll
    for (int q = 0; q < 4; q++)
        dst[q] = make_uint4(u[q * 4], u[q * 4 + 1], u[q * 4 + 2], u[q * 4 + 3]);
}

// ---------------- kernel 2: pure fp16 mma GEMM, 3-stage cp.async ----------
// Stage: A 256*144 = 36864 B, B 128*144 = 18432 B -> 55296/stage, 3 stages.
#define ST_A 36864u
#define ST_B 18432u
#define ST_SZ (ST_A + ST_B)
#define SMEM_BYTES (3 * (36864 + 18432))   // 165888

__global__ void __launch_bounds__(THREADS, 1)
gegen_kernel(float* __restrict__ out) {
    extern __shared__ __align__(16) char smem[];
    const uint32_t sb = smem_u32(smem);
    const int tid  = threadIdx.x;
    const int lane = tid & 31;
    const int wid  = tid >> 5;
    const int o0 = blockIdx.x * TILE_N;   // N-block fastest -> co-resident CTAs share A
    const int b0 = blockIdx.y * TILE_M;
    const int wm = (wid & 3) * 64;
    const int wn = (wid >> 2) * 64;

    float acc[4][8][4];
#pragma unroll
    for (int mf = 0; mf < 4; mf++)
#pragma unroll
        for (int nf = 0; nf < 8; nf++)
#pragma unroll
            for (int j = 0; j < 4; j++) acc[mf][nf][j] = 0.0f;

    // ---- ldmatrix per-lane offsets (relative to stage base) ----
    const int a_r = lane & 15;
    const int a_c = (lane >> 4) * 16;
    uint32_t aoff[4];
#pragma unroll
    for (int mf = 0; mf < 4; mf++)
        aoff[mf] = (uint32_t)(wm + mf * 16 + a_r) * PITCH + a_c;
    const int b_r = (lane & 7) + ((lane >> 4) & 1) * 8;
    const int b_c = ((lane >> 3) & 1) * 16;
    uint32_t boff[4];
#pragma unroll
    for (int p = 0; p < 4; p++)
        boff[p] = (uint32_t)(wn + p * 16 + b_r) * PITCH + b_c;

    // ---- cp.async mapping: 8 threads per row, full 128B contiguous/row ----
    const int crow = tid >> 3;          // 0..31 (row group base)
    const int cseg = tid & 7;           // 16B segment within row
    const __half* pA = g_A  + ((size_t)(b0 + crow) << 12) + cseg * 8;
    const __half* pB = g_Wh + ((size_t)(o0 + crow) << 12) + cseg * 8;
    const uint32_t a_dst = (uint32_t)crow * PITCH + cseg * 16;  // + j*32*PITCH
    // j-th instruction covers rows j*32 .. j*32+31

    auto issue = [&](int c, uint32_t stBase) {
        const uint32_t aBuf = stBase, bBuf = stBase + ST_A;
        const size_t koff = (size_t)c * KC;
#pragma unroll
        for (int j = 0; j < 8; j++) {   // A: 256 rows
            asm volatile("cp.async.cg.shared.global [%0], [%1], 16;"
                         :: "r"(aBuf + a_dst + j * (32 * PITCH)),
                            "l"(pA + ((size_t)j << 17) + koff) : "memory");
        }
#pragma unroll
        for (int j = 0; j < 4; j++) {   // B: 128 rows
            asm volatile("cp.async.cg.shared.global [%0], [%1], 16;"
                         :: "r"(bBuf + a_dst + j * (32 * PITCH)),
                            "l"(pB + ((size_t)j << 17) + koff) : "memory");
        }
        asm volatile("cp.async.commit_group;" ::: "memory");
    };

    auto consume = [&](uint32_t stBase) {
        const uint32_t aBuf = stBase, bBuf = stBase + ST_A;
#pragma unroll
        for (int ks = 0; ks < 4; ks++) {
            const uint32_t koff = ks * 32;
            uint32_t a[4][4], b[4][4];
#pragma unroll
            for (int mf = 0; mf < 4; mf++) ldsm4(a[mf], aBuf + aoff[mf] + koff);
#pragma unroll
            for (int p = 0; p < 4; p++)   ldsm4(b[p], bBuf + boff[p] + koff);
#pragma unroll
            for (int mf = 0; mf < 4; mf++)
#pragma unroll
                for (int nf = 0; nf < 8; nf++)
                    mma16(acc[mf][nf], a[mf], &b[nf >> 1][(nf & 1) * 2]);
        }
    };

    uint32_t stage[3] = {sb, sb + ST_SZ, sb + 2 * ST_SZ};

    // ---- prologue: 2 chunks in flight ----
    issue(0, stage[0]);
    issue(1, stage[1]);

    // ---- main loop ----
#pragma unroll 1
    for (int c = 0; c < NCHUNK; c++) {
        if (c + 1 < NCHUNK) {
            asm volatile("cp.async.wait_group 1;" ::: "memory");  // chunk c landed
        } else {
            asm volatile("cp.async.wait_group 0;" ::: "memory");
        }
        __syncthreads();   // all threads see chunk c; stage (c+2)%3 free

        if (c + 2 < NCHUNK) issue(c + 2, stage[(c + 2) % 3]);

        consume(stage[c % 3]);
    }

    // ---- epilogue: scale back and store ----
#pragma unroll
    for (int mf = 0; mf < 4; mf++) {
        const int rbase = b0 + wm + mf * 16 + (lane >> 2);
#pragma unroll
        for (int h = 0; h < 2; h++) {
            float* op = out + (size_t)(rbase + h * 8) * O_DIM
                            + o0 + wn + (lane & 3) * 2;
#pragma unroll
            for (int nf = 0; nf < 8; nf++) {
                float2 v;
                v.x = acc[mf][nf][h * 2]     * OUT_SCALE;
                v.y = acc[mf][nf][h * 2 + 1] * OUT_SCALE;
                *reinterpret_cast<float2*>(op + nf * 8) = v;
            }
        }
    }
}

// ---------------- launch ----------------
extern "C" void kernel_launch(void* const* d_in, const int* in_sizes, int n_in,
                              void* d_out, int out_size) {
    const float* x      = (const float*)d_in[0];
    const float* coeffs = (const float*)d_in[1];
    float* out          = (float*)d_out;

    const int B = in_sizes[0] / I_DIM;   // 16384

    prep_kernel<<<(I_DIM * O_DIM * 8) / 256, 256>>>(coeffs);
    poly_kernel<<<(B * 128) / 256, 256>>>(x);

    cudaFuncSetAttribute(gegen_kernel,
                         cudaFuncAttributeMaxDynamicSharedMemorySize, SMEM_BYTES);

    dim3 grid(O_DIM / TILE_N, B / TILE_M);   // x = N-block (co-residency on A rows)
    gegen_kernel<<<grid, THREADS, SMEM_BYTES>>>(out);
}